// round 15
// baseline (speedup 1.0000x reference)
#include <cuda_runtime.h>
#include <cstdint>
#include <math.h>

#define BB   32
#define PP   6
#define DD   96
#define EE   128
#define HH   8
#define HD   16
#define II   64
#define KK   32
#define LL   768
#define BLR  (BB*LL)      // 24576 rows
#define OUTN 128

typedef unsigned long long u64;
__device__ __forceinline__ u64 pack2(float lo, float hi){
    u64 r; asm("mov.b64 %0,{%1,%2};" : "=l"(r) : "f"(lo), "f"(hi)); return r;
}
__device__ __forceinline__ void unpack2(u64 v, float& lo, float& hi){
    asm("mov.b64 {%0,%1},%2;" : "=f"(lo), "=f"(hi) : "l"(v));
}
__device__ __forceinline__ u64 ffma2(u64 a, u64 b, u64 c){
    u64 d; asm("fma.rn.f32x2 %0,%1,%2,%3;" : "=l"(d) : "l"(a), "l"(b), "l"(c)); return d;
}
__device__ __forceinline__ float ex2f(float x){
    float r; asm("ex2.approx.f32 %0, %1;" : "=f"(r) : "f"(x)); return r;
}
__device__ __forceinline__ uint32_t tf32c(float x){
    uint32_t r; asm("cvt.rna.tf32.f32 %0, %1;" : "=r"(r) : "f"(x)); return r;
}
__device__ __forceinline__ void mma8(float* d, uint32_t a0, uint32_t a1,
                                     uint32_t a2, uint32_t a3,
                                     uint32_t b0, uint32_t b1){
    asm volatile("mma.sync.aligned.m16n8k8.row.col.f32.tf32.tf32.f32 "
        "{%0,%1,%2,%3},{%4,%5,%6,%7},{%8,%9},{%0,%1,%2,%3};"
        : "+f"(d[0]), "+f"(d[1]), "+f"(d[2]), "+f"(d[3])
        : "r"(a0), "r"(a1), "r"(a2), "r"(a3), "r"(b0), "r"(b1));
}

// ---------------- scratch ----------------
__device__ float g_seq  [BLR*EE];
__device__ float g_qkv  [BLR*3*EE];
__device__ float g_ctx  [BLR*EE];
__device__ float g_hid  [BLR*II];
__device__ float g_pn   [DD*KK*PP];
__device__ float g_pos  [LL*EE];
__device__ float g_part [LL*BB*OUTN];

// ---------------- prototype normalization ----------------
__global__ void proto_norm_kernel(const float* __restrict__ proto) {
    int i = blockIdx.x * 256 + threadIdx.x;
    if (i >= DD*KK) return;
    float v[PP]; float n2 = 0.f;
#pragma unroll
    for (int p = 0; p < PP; p++) { v[p] = proto[i*PP + p]; n2 += v[p]*v[p]; }
    float nr = fmaxf(sqrtf(n2), 1e-12f);
#pragma unroll
    for (int p = 0; p < PP; p++) g_pn[i*PP + p] = v[p] / nr;
}

// ---------------- positional encoding ----------------
__global__ void pos_kernel() {
    int i = blockIdx.x * 256 + threadIdx.x;
    int l = i >> 7, e = i & 127;
    int half = e >> 1;
    float freq = expf(-(float)(2*half) * (logf(10000.0f) / (float)EE));
    float ang = (float)l * freq;
    g_pos[i] = (e & 1) ? cosf(ang) : sinf(ang);
}

// ---------------- embedding ----------------
__global__ __launch_bounds__(256)
void embed_kernel(const float* __restrict__ x,
                  const float* __restrict__ emb_w, const float* __restrict__ emb_b,
                  const float* __restrict__ proj_w, const float* __restrict__ proj_b)
{
    int gwarp = (blockIdx.x * blockDim.x + threadIdx.x) >> 5;
    int lane  = threadIdx.x & 31;
    if (gwarp >= BLR) return;
    int rid = gwarp;
    int d = rid % DD;
    int l = rid % LL;

    float xr[PP]; float n2 = 0.f;
#pragma unroll
    for (int p = 0; p < PP; p++) { xr[p] = x[(size_t)rid*PP + p]; n2 += xr[p]*xr[p]; }
    float nr = fmaxf(sqrtf(n2), 1e-12f);
    float xn[PP];
#pragma unroll
    for (int p = 0; p < PP; p++) xn[p] = xr[p] / nr;

    const float* pn = g_pn + (size_t)d * KK * PP;
    float s = 0.f;
#pragma unroll
    for (int p = 0; p < PP; p++) s += xn[p] * pn[lane*PP + p];

    float bv = s; int bi = lane;
#pragma unroll
    for (int o = 16; o > 0; o >>= 1) {
        float ov = __shfl_xor_sync(0xffffffffu, bv, o);
        int   oi = __shfl_xor_sync(0xffffffffu, bi, o);
        if (ov > bv || (ov == bv && oi < bi)) { bv = ov; bi = oi; }
    }
    float sel[PP];
#pragma unroll
    for (int p = 0; p < PP; p++) sel[p] = pn[bi*PP + p];

#pragma unroll
    for (int j = 0; j < 4; j++) {
        int e = lane + (j << 5);
        float v = emb_b[e] + proj_b[e] + g_pos[l*EE + e];
#pragma unroll
        for (int p = 0; p < PP; p++)
            v += xr[p] * emb_w[e*PP + p] + sel[p] * proj_w[e*PP + p];
        g_seq[(size_t)rid*EE + e] = v;
    }
}

// ========== tf32 mma GEMM v4: C[M,N] = A[M,Kd] @ W[N,Kd]^T + bias ============
// 256 threads = 8 warps, each warp owns 16 rows (1 m-frag). B pre-packed in
// fragment order (per-lane stride NFp = 4*odd -> conflict-free LDS.128).
// ACT=1: ELU. FLN=1: fused residual+layernorm (NT==N==128; C in place).
template <int NT, int ACT, int FLN>
__global__ __launch_bounds__(256, 2)
void mma_gemm4(const float* __restrict__ A, const float* __restrict__ W,
               const float* __restrict__ bias, float* __restrict__ C,
               const float* __restrict__ gam, const float* __restrict__ bet,
               int N, int Kd)
{
    constexpr int NF  = NT/8;                 // 16 or 8
    constexpr int NFp = (NF == 16) ? 20 : 12; // 4*odd: conflict-free vec4 LDS
    constexpr int SA  = 132;
    __shared__ __align__(16) uint32_t As [32*SA];
    __shared__ __align__(16) uint32_t Bp0[4*32*NFp];
    __shared__ __align__(16) uint32_t Bp1[4*32*NFp];
    int tid = threadIdx.x;
    int w = tid >> 5, lane = tid & 31;
    int lq = lane >> 2, lr = lane & 3;
    int m0 = blockIdx.y << 7, n0 = blockIdx.x * NT;
    int mw = w << 4;

    float acc[NF][4];
#pragma unroll
    for (int j = 0; j < NF; j++)
#pragma unroll
        for (int t = 0; t < 4; t++) acc[j][t] = 0.f;

    for (int k0 = 0; k0 < Kd; k0 += 32) {
#pragma unroll
        for (int i = 0; i < 4; i++) {               // A: 128 rows x 32 k
            int idx = tid + (i << 8);
            int m = idx >> 3, g = idx & 7;
            float4 v = *(const float4*)(A + (size_t)(m0 + m) * Kd + k0 + g*4);
            As[(g*4+0)*SA + m] = tf32c(v.x);
            As[(g*4+1)*SA + m] = tf32c(v.y);
            As[(g*4+2)*SA + m] = tf32c(v.z);
            As[(g*4+3)*SA + m] = tf32c(v.w);
        }
#pragma unroll
        for (int i = 0; i < NT/32; i++) {           // B: NT rows x 32 k, packed
            int idx = tid + (i << 8);
            int n = idx >> 3, g = idx & 7;
            float4 v = *(const float4*)(W + (size_t)(n0 + n) * Kd + k0 + g*4);
            uint32_t* dst = ((g & 1) ? Bp1 : Bp0)
                          + (((g >> 1)*32) + ((n & 7) << 2))*NFp + (n >> 3);
            dst[0*NFp] = tf32c(v.x);
            dst[1*NFp] = tf32c(v.y);
            dst[2*NFp] = tf32c(v.z);
            dst[3*NFp] = tf32c(v.w);
        }
        __syncthreads();
#pragma unroll
        for (int k8 = 0; k8 < 4; k8++) {
            int kk = k8*8;
            uint32_t a0 = As[(kk + lr)*SA + mw + lq];
            uint32_t a1 = As[(kk + lr)*SA + mw + 8 + lq];
            uint32_t a2 = As[(kk + 4 + lr)*SA + mw + lq];
            uint32_t a3 = As[(kk + 4 + lr)*SA + mw + 8 + lq];
            const uint32_t* bp0 = Bp0 + (k8*32 + lane)*NFp;
            const uint32_t* bp1 = Bp1 + (k8*32 + lane)*NFp;
#pragma unroll
            for (int jv = 0; jv < NF/4; jv++) {
                uint4 b0v = *(const uint4*)(bp0 + jv*4);
                uint4 b1v = *(const uint4*)(bp1 + jv*4);
                mma8(acc[jv*4+0], a0, a1, a2, a3, b0v.x, b1v.x);
                mma8(acc[jv*4+1], a0, a1, a2, a3, b0v.y, b1v.y);
                mma8(acc[jv*4+2], a0, a1, a2, a3, b0v.z, b1v.z);
                mma8(acc[jv*4+3], a0, a1, a2, a3, b0v.w, b1v.w);
            }
        }
        __syncthreads();
    }

    int r0 = m0 + mw + lq;
    int cb = 2*lr;

    if (!FLN) {
#pragma unroll
        for (int j = 0; j < NF; j++) {
            int n = n0 + j*8 + cb;
            float2 bv = *(const float2*)(bias + n);
            float x0 = acc[j][0] + bv.x, x1 = acc[j][1] + bv.y;
            float x2 = acc[j][2] + bv.x, x3 = acc[j][3] + bv.y;
            if (ACT) {
                x0 = (x0 > 0.f) ? x0 : expm1f(x0);
                x1 = (x1 > 0.f) ? x1 : expm1f(x1);
                x2 = (x2 > 0.f) ? x2 : expm1f(x2);
                x3 = (x3 > 0.f) ? x3 : expm1f(x3);
            }
            float2 o0; o0.x = x0; o0.y = x1;
            float2 o1; o1.x = x2; o1.y = x3;
            *(float2*)(C + (size_t)r0 * N + n)     = o0;
            *(float2*)(C + (size_t)(r0+8) * N + n) = o1;
        }
    } else {
        float s0 = 0.f, s1 = 0.f;
#pragma unroll
        for (int j = 0; j < NF; j++) {
            int n = j*8 + cb;
            float2 bv = *(const float2*)(bias + n);
            float2 e0 = *(const float2*)(C + (size_t)r0*128 + n);
            float2 e1 = *(const float2*)(C + (size_t)(r0+8)*128 + n);
            acc[j][0] += bv.x + e0.x;  acc[j][1] += bv.y + e0.y;
            acc[j][2] += bv.x + e1.x;  acc[j][3] += bv.y + e1.y;
            s0 += acc[j][0] + acc[j][1];
            s1 += acc[j][2] + acc[j][3];
        }
        s0 += __shfl_xor_sync(0xffffffffu, s0, 1);
        s0 += __shfl_xor_sync(0xffffffffu, s0, 2);
        s1 += __shfl_xor_sync(0xffffffffu, s1, 1);
        s1 += __shfl_xor_sync(0xffffffffu, s1, 2);
        float mean0 = s0 * (1.0f/128.0f);
        float mean1 = s1 * (1.0f/128.0f);
        float q0 = 0.f, q1 = 0.f;
#pragma unroll
        for (int j = 0; j < NF; j++) {
            acc[j][0] -= mean0; acc[j][1] -= mean0;
            acc[j][2] -= mean1; acc[j][3] -= mean1;
            q0 += acc[j][0]*acc[j][0] + acc[j][1]*acc[j][1];
            q1 += acc[j][2]*acc[j][2] + acc[j][3]*acc[j][3];
        }
        q0 += __shfl_xor_sync(0xffffffffu, q0, 1);
        q0 += __shfl_xor_sync(0xffffffffu, q0, 2);
        q1 += __shfl_xor_sync(0xffffffffu, q1, 1);
        q1 += __shfl_xor_sync(0xffffffffu, q1, 2);
        float rstd0 = rsqrtf(q0 * (1.0f/128.0f) + 1e-5f);
        float rstd1 = rsqrtf(q1 * (1.0f/128.0f) + 1e-5f);
#pragma unroll
        for (int j = 0; j < NF; j++) {
            int n = j*8 + cb;
            float2 gv = *(const float2*)(gam + n);
            float2 bt = *(const float2*)(bet + n);
            float2 o0, o1;
            o0.x = acc[j][0]*rstd0*gv.x + bt.x;
            o0.y = acc[j][1]*rstd0*gv.y + bt.y;
            o1.x = acc[j][2]*rstd1*gv.x + bt.x;
            o1.y = acc[j][3]*rstd1*gv.y + bt.y;
            *(float2*)(C + (size_t)r0*128 + n)     = o0;
            *(float2*)(C + (size_t)(r0+8)*128 + n) = o1;
        }
    }
}

// ========== attention on mma.sync: block=(qtile,h,b), 256 thr, 8 warps ========
#define ACH 64
#define NCHUNK (LL/ACH)   // 12
__global__ __launch_bounds__(256)
void attn_mma_kernel(const float* __restrict__ qkv, float* __restrict__ ctx)
{
    __shared__ uint32_t Ks[ACH*20];
    __shared__ uint32_t Vs[ACH*24];
    int qt = blockIdx.x, h = blockIdx.y, b = blockIdx.z;
    int tid = threadIdx.x;
    int w = tid >> 5, lane = tid & 31;
    int lq = lane >> 2, lr = lane & 3;
    const float SC = 0.25f * 1.4426950408889634f;
    const float* base = qkv + (size_t)b * LL * (3*EE) + h*HD;

    uint32_t qa[2][4];
    {
        const float* q0 = base + (size_t)(qt*128 + w*16 + lq) * (3*EE);
        const float* q1 = q0 + (size_t)8 * (3*EE);
#pragma unroll
        for (int ks = 0; ks < 2; ks++) {
            qa[ks][0] = tf32c(q0[ks*8 + lr]     * SC);
            qa[ks][1] = tf32c(q1[ks*8 + lr]     * SC);
            qa[ks][2] = tf32c(q0[ks*8 + 4 + lr] * SC);
            qa[ks][3] = tf32c(q1[ks*8 + 4 + lr] * SC);
        }
    }

    float acc[2][4];
#pragma unroll
    for (int nf = 0; nf < 2; nf++)
#pragma unroll
        for (int t = 0; t < 4; t++) acc[nf][t] = 0.f;
    float s0 = 0.f, s1 = 0.f;

    for (int c = 0; c < NCHUNK; c++) {
        __syncthreads();
        {
            int m = tid >> 2, part = (tid & 3) << 2;
            const float* kp = base + (size_t)(c*ACH + m) * (3*EE) + EE + part;
            float4 kv = *(const float4*)kp;
            float4 vv = *(const float4*)(kp + EE);
            Ks[m*20 + part + 0] = tf32c(kv.x);
            Ks[m*20 + part + 1] = tf32c(kv.y);
            Ks[m*20 + part + 2] = tf32c(kv.z);
            Ks[m*20 + part + 3] = tf32c(kv.w);
            Vs[m*24 + part + 0] = tf32c(vv.x);
            Vs[m*24 + part + 1] = tf32c(vv.y);
            Vs[m*24 + part + 2] = tf32c(vv.z);
            Vs[m*24 + part + 3] = tf32c(vv.w);
        }
        __syncthreads();

#pragma unroll
        for (int j = 0; j < 8; j++) {
            float sf[4] = {0.f, 0.f, 0.f, 0.f};
#pragma unroll
            for (int ks = 0; ks < 2; ks++) {
                uint32_t b0 = Ks[(j*8 + lq)*20 + ks*8 + lr];
                uint32_t b1 = Ks[(j*8 + lq)*20 + ks*8 + 4 + lr];
                mma8(sf, qa[ks][0], qa[ks][1], qa[ks][2], qa[ks][3], b0, b1);
            }
            float e0 = ex2f(sf[0]), e1 = ex2f(sf[1]);
            float e2 = ex2f(sf[2]), e3 = ex2f(sf[3]);
            s0 += e0 + e1;  s1 += e2 + e3;
            uint32_t f0 = tf32c(e0), f1 = tf32c(e1);
            uint32_t f2 = tf32c(e2), f3 = tf32c(e3);
            int src0 = (lane & 28) | (lr >> 1);
            int src2 = src0 + 2;
            uint32_t t00 = __shfl_sync(0xffffffffu, f0, src0);
            uint32_t t01 = __shfl_sync(0xffffffffu, f1, src0);
            uint32_t t02 = __shfl_sync(0xffffffffu, f2, src0);
            uint32_t t03 = __shfl_sync(0xffffffffu, f3, src0);
            uint32_t t20 = __shfl_sync(0xffffffffu, f0, src2);
            uint32_t t21 = __shfl_sync(0xffffffffu, f1, src2);
            uint32_t t22 = __shfl_sync(0xffffffffu, f2, src2);
            uint32_t t23 = __shfl_sync(0xffffffffu, f3, src2);
            bool odd = (lr & 1);
            uint32_t a0 = odd ? t01 : t00;
            uint32_t a1 = odd ? t03 : t02;
            uint32_t a2 = odd ? t21 : t20;
            uint32_t a3 = odd ? t23 : t22;
#pragma unroll
            for (int nf = 0; nf < 2; nf++) {
                uint32_t b0 = Vs[(j*8 + lr)*24 + nf*8 + lq];
                uint32_t b1 = Vs[(j*8 + 4 + lr)*24 + nf*8 + lq];
                mma8(acc[nf], a0, a1, a2, a3, b0, b1);
            }
        }
    }

    s0 += __shfl_xor_sync(0xffffffffu, s0, 1);
    s0 += __shfl_xor_sync(0xffffffffu, s0, 2);
    s1 += __shfl_xor_sync(0xffffffffu, s1, 1);
    s1 += __shfl_xor_sync(0xffffffffu, s1, 2);
    float inv0 = 1.0f / s0, inv1 = 1.0f / s1;

    float* o0 = ctx + (size_t)(b*LL + qt*128 + w*16 + lq) * EE + h*HD;
    float* o1 = o0 + (size_t)8 * EE;
#pragma unroll
    for (int nf = 0; nf < 2; nf++) {
        float2 r0; r0.x = acc[nf][0] * inv0;  r0.y = acc[nf][1] * inv0;
        float2 r1; r1.x = acc[nf][2] * inv1;  r1.y = acc[nf][3] * inv1;
        *(float2*)(o0 + nf*8 + 2*lr) = r0;
        *(float2*)(o1 + nf*8 + 2*lr) = r1;
    }
}

// ========== final projection on mma: block per l, 128 thr, 4 warps ===========
__global__ __launch_bounds__(128)
void final_mma(const float* __restrict__ seq, const float* __restrict__ ow,
               float* __restrict__ part)
{
    constexpr int NFp = 20;
    constexpr int SAE = 36;
    __shared__ __align__(16) uint32_t Ae [128*SAE];
    __shared__ __align__(16) uint32_t Bp0[4*32*NFp];
    __shared__ __align__(16) uint32_t Bp1[4*32*NFp];
    int l = blockIdx.x, tid = threadIdx.x;
    int w = tid >> 5, lane = tid & 31;
    int lq = lane >> 2, lr = lane & 3;

#pragma unroll
    for (int i = 0; i < 8; i++) {
        int idx = tid + (i << 7);
        int b = idx >> 5, g = idx & 31;
        float4 v = *(const float4*)(seq + (size_t)b*(LL*EE) + l*EE + g*4);
        Ae[(g*4+0)*SAE + b] = tf32c(v.x);
        Ae[(g*4+1)*SAE + b] = tf32c(v.y);
        Ae[(g*4+2)*SAE + b] = tf32c(v.z);
        Ae[(g*4+3)*SAE + b] = tf32c(v.w);
    }

    float acc[2][4][4];
#pragma unroll
    for (int f = 0; f < 2; f++)
#pragma unroll
        for (int j = 0; j < 4; j++)
#pragma unroll
            for (int t = 0; t < 4; t++) acc[f][j][t] = 0.f;

    for (int k0 = 0; k0 < 128; k0 += 32) {
#pragma unroll
        for (int i = 0; i < 8; i++) {
            int idx = tid + (i << 7);
            int n = idx >> 3, g = idx & 7;
            float4 v = *(const float4*)(ow + (size_t)n*(LL*EE) + l*EE + k0 + g*4);
            uint32_t* dst = ((g & 1) ? Bp1 : Bp0)
                          + (((g >> 1)*32) + ((n & 7) << 2))*NFp + (n >> 3);
            dst[0*NFp] = tf32c(v.x);
            dst[1*NFp] = tf32c(v.y);
            dst[2*NFp] = tf32c(v.z);
            dst[3*NFp] = tf32c(v.w);
        }
        __syncthreads();
#pragma unroll
        for (int k8 = 0; k8 < 4; k8++) {
            int kk = k0 + k8*8;
            uint32_t a0[4], a1[4];
            a0[0] = Ae[(kk + lr)*SAE + lq];
            a0[1] = Ae[(kk + lr)*SAE + 8 + lq];
            a0[2] = Ae[(kk + 4 + lr)*SAE + lq];
            a0[3] = Ae[(kk + 4 + lr)*SAE + 8 + lq];
            a1[0] = Ae[(kk + lr)*SAE + 16 + lq];
            a1[1] = Ae[(kk + lr)*SAE + 24 + lq];
            a1[2] = Ae[(kk + 4 + lr)*SAE + 16 + lq];
            a1[3] = Ae[(kk + 4 + lr)*SAE + 24 + lq];
            const uint32_t* bp0 = Bp0 + (k8*32 + lane)*NFp + (w << 2);
            const uint32_t* bp1 = Bp1 + (k8*32 + lane)*NFp + (w << 2);
            uint4 b0v = *(const uint4*)bp0;
            uint4 b1v = *(const uint4*)bp1;
            mma8(acc[0][0], a0[0],a0[1],a0[2],a0[3], b0v.x, b1v.x);
            mma8(acc[1][0], a1[0],a1[1],a1[2],a1[3], b0v.x, b1v.x);
            mma8(acc[0][1], a0[0],a0[1],a0[2],a0[3], b0v.y, b1v.y);
            mma8(acc[1][1], a1[0],a1[1],a1[2],a1[3], b0v.y, b1v.y);
            mma8(acc[0][2], a0[0],a0[1],a0[2],a0[3], b0v.z, b1v.z);
            mma8(acc[1][2], a1[0],a1[1],a1[2],a1[3], b0v.z, b1v.z);
            mma8(acc[0][3], a0[0],a0[1],a0[2],a0[3], b0v.w, b1v.w);
            mma8(acc[1][3], a1[0],a1[1],a1[2],a1[3], b0v.w, b1v.w);
        }
        __syncthreads();
    }

    float* dst = part + (size_t)l * (BB*OUTN);
#pragma unroll
    for (int f = 0; f < 2; f++) {
        int br = f*16 + lq;
#pragma unroll
        for (int j = 0; j < 4; j++) {
            int o = (w << 5) + j*8 + 2*lr;
            float2 v0; v0.x = acc[f][j][0]; v0.y = acc[f][j][1];
            float2 v1; v1.x = acc[f][j][2]; v1.y = acc[f][j][3];
            *(float2*)(dst + br*OUTN + o)     = v0;
            *(float2*)(dst + (br+8)*OUTN + o) = v1;
        }
    }
}

// ---------------- final reduce: one warp per output ----------------
__global__ __launch_bounds__(256)
void final_reduce2(const float* __restrict__ part,
                   const float* __restrict__ out_b, float* __restrict__ out)
{
    int gw = (blockIdx.x * 256 + threadIdx.x) >> 5;
    int lane = threadIdx.x & 31;
    float s = 0.f;
#pragma unroll
    for (int t = 0; t < 24; t++)
        s += part[(size_t)(lane + t*32) * (BB*OUTN) + gw];
#pragma unroll
    for (int o = 16; o > 0; o >>= 1) s += __shfl_xor_sync(0xffffffffu, s, o);
    if (lane == 0) out[gw] = s + out_b[gw & 127];
}

// ---------------- host launcher ----------------
extern "C" void kernel_launch(void* const* d_in, const int* in_sizes, int n_in,
                              void* d_out, int out_size)
{
    const float* x          = (const float*)d_in[0];
    const float* prototypes = (const float*)d_in[1];
    const float* emb_w      = (const float*)d_in[2];
    const float* emb_b      = (const float*)d_in[3];
    const float* proj_w     = (const float*)d_in[4];
    const float* proj_b     = (const float*)d_in[5];
    const float* in_proj_w  = (const float*)d_in[6];
    const float* in_proj_b  = (const float*)d_in[7];
    const float* out_proj_w = (const float*)d_in[8];
    const float* out_proj_b = (const float*)d_in[9];
    const float* ln1_s      = (const float*)d_in[10];
    const float* ln1_b      = (const float*)d_in[11];
    const float* ffn_w1     = (const float*)d_in[12];
    const float* ffn_b1     = (const float*)d_in[13];
    const float* ffn_w2     = (const float*)d_in[14];
    const float* ffn_b2     = (const float*)d_in[15];
    const float* ln2_s      = (const float*)d_in[16];
    const float* ln2_b      = (const float*)d_in[17];
    const float* out_w      = (const float*)d_in[18];
    const float* out_b      = (const float*)d_in[19];
    float* out = (float*)d_out;

    float *seq, *qkv, *ctx, *hid, *part;
    cudaGetSymbolAddress((void**)&seq,   g_seq);
    cudaGetSymbolAddress((void**)&qkv,   g_qkv);
    cudaGetSymbolAddress((void**)&ctx,   g_ctx);
    cudaGetSymbolAddress((void**)&hid,   g_hid);
    cudaGetSymbolAddress((void**)&part,  g_part);

    proto_norm_kernel<<<12, 256>>>(prototypes);
    pos_kernel<<<(LL*EE)/256, 256>>>();
    embed_kernel<<<BLR/8, 256>>>(x, emb_w, emb_b, proj_w, proj_b);

    for (int l = 0; l < 2; l++) {
        // qkv = seq @ in_proj_w[l]^T + b   (M=24576, N=384, K=128)
        mma_gemm4<128,0,0><<<dim3(3, BLR/128), 256>>>(
            seq, in_proj_w + (size_t)l*3*EE*EE, in_proj_b + l*3*EE, qkv,
            nullptr, nullptr, 3*EE, EE);
        attn_mma_kernel<<<dim3(LL/128, HH, BB), 256>>>(qkv, ctx);
        // seq = LN1(seq + ctx @ out_proj_w[l]^T + b)   (fused)
        mma_gemm4<128,0,1><<<dim3(1, BLR/128), 256>>>(
            ctx, out_proj_w + (size_t)l*EE*EE, out_proj_b + l*EE, seq,
            ln1_s + l*EE, ln1_b + l*EE, EE, EE);
        // hid = elu(seq @ w1^T + b1)   (N=64, K=128)
        mma_gemm4<64,1,0><<<dim3(1, BLR/128), 256>>>(
            seq, ffn_w1 + (size_t)l*II*EE, ffn_b1 + l*II, hid,
            nullptr, nullptr, II, EE);
        // seq = LN2(seq + hid @ w2^T + b2)   (fused; K=64)
        mma_gemm4<128,0,1><<<dim3(1, BLR/128), 256>>>(
            hid, ffn_w2 + (size_t)l*EE*II, ffn_b2 + l*EE, seq,
            ln2_s + l*EE, ln2_b + l*EE, EE, II);
    }

    final_mma<<<LL, 128>>>(seq, out_w, part);
    final_reduce2<<<(BB*OUTN*32)/256, 256>>>(part, out_b, out);
}

// round 16
// speedup vs baseline: 1.0052x; 1.0052x over previous
#include <cuda_runtime.h>
#include <cstdint>
#include <math.h>

#define BB   32
#define PP   6
#define DD   96
#define EE   128
#define HH   8
#define HD   16
#define II   64
#define KK   32
#define LL   768
#define BLR  (BB*LL)      // 24576 rows
#define OUTN 128

typedef unsigned long long u64;
__device__ __forceinline__ u64 pack2(float lo, float hi){
    u64 r; asm("mov.b64 %0,{%1,%2};" : "=l"(r) : "f"(lo), "f"(hi)); return r;
}
__device__ __forceinline__ void unpack2(u64 v, float& lo, float& hi){
    asm("mov.b64 {%0,%1},%2;" : "=f"(lo), "=f"(hi) : "l"(v));
}
__device__ __forceinline__ u64 ffma2(u64 a, u64 b, u64 c){
    u64 d; asm("fma.rn.f32x2 %0,%1,%2,%3;" : "=l"(d) : "l"(a), "l"(b), "l"(c)); return d;
}
__device__ __forceinline__ float ex2f(float x){
    float r; asm("ex2.approx.f32 %0, %1;" : "=f"(r) : "f"(x)); return r;
}
__device__ __forceinline__ uint32_t tf32c(float x){
    uint32_t r; asm("cvt.rna.tf32.f32 %0, %1;" : "=r"(r) : "f"(x)); return r;
}
__device__ __forceinline__ void mma8(float* d, uint32_t a0, uint32_t a1,
                                     uint32_t a2, uint32_t a3,
                                     uint32_t b0, uint32_t b1){
    asm volatile("mma.sync.aligned.m16n8k8.row.col.f32.tf32.tf32.f32 "
        "{%0,%1,%2,%3},{%4,%5,%6,%7},{%8,%9},{%0,%1,%2,%3};"
        : "+f"(d[0]), "+f"(d[1]), "+f"(d[2]), "+f"(d[3])
        : "r"(a0), "r"(a1), "r"(a2), "r"(a3), "r"(b0), "r"(b1));
}

// ---------------- scratch ----------------
__device__ float g_seq  [BLR*EE];
__device__ float g_qkv  [BLR*3*EE];
__device__ float g_ctx  [BLR*EE];
__device__ float g_hid  [BLR*II];
__device__ float g_pn   [DD*KK*PP];
__device__ float g_pos  [LL*EE];
__device__ float g_part [LL*BB*OUTN];

// ---------------- prototype normalization ----------------
__global__ void proto_norm_kernel(const float* __restrict__ proto) {
    int i = blockIdx.x * 256 + threadIdx.x;
    if (i >= DD*KK) return;
    float v[PP]; float n2 = 0.f;
#pragma unroll
    for (int p = 0; p < PP; p++) { v[p] = proto[i*PP + p]; n2 += v[p]*v[p]; }
    float nr = fmaxf(sqrtf(n2), 1e-12f);
#pragma unroll
    for (int p = 0; p < PP; p++) g_pn[i*PP + p] = v[p] / nr;
}

// ---------------- positional encoding ----------------
__global__ void pos_kernel() {
    int i = blockIdx.x * 256 + threadIdx.x;
    int l = i >> 7, e = i & 127;
    int half = e >> 1;
    float freq = expf(-(float)(2*half) * (logf(10000.0f) / (float)EE));
    float ang = (float)l * freq;
    g_pos[i] = (e & 1) ? cosf(ang) : sinf(ang);
}

// ---------------- embedding ----------------
__global__ __launch_bounds__(256)
void embed_kernel(const float* __restrict__ x,
                  const float* __restrict__ emb_w, const float* __restrict__ emb_b,
                  const float* __restrict__ proj_w, const float* __restrict__ proj_b)
{
    int gwarp = (blockIdx.x * blockDim.x + threadIdx.x) >> 5;
    int lane  = threadIdx.x & 31;
    if (gwarp >= BLR) return;
    int rid = gwarp;
    int d = rid % DD;
    int l = rid % LL;

    float xr[PP]; float n2 = 0.f;
#pragma unroll
    for (int p = 0; p < PP; p++) { xr[p] = x[(size_t)rid*PP + p]; n2 += xr[p]*xr[p]; }
    float nr = fmaxf(sqrtf(n2), 1e-12f);
    float xn[PP];
#pragma unroll
    for (int p = 0; p < PP; p++) xn[p] = xr[p] / nr;

    const float* pn = g_pn + (size_t)d * KK * PP;
    float s = 0.f;
#pragma unroll
    for (int p = 0; p < PP; p++) s += xn[p] * pn[lane*PP + p];

    float bv = s; int bi = lane;
#pragma unroll
    for (int o = 16; o > 0; o >>= 1) {
        float ov = __shfl_xor_sync(0xffffffffu, bv, o);
        int   oi = __shfl_xor_sync(0xffffffffu, bi, o);
        if (ov > bv || (ov == bv && oi < bi)) { bv = ov; bi = oi; }
    }
    float sel[PP];
#pragma unroll
    for (int p = 0; p < PP; p++) sel[p] = pn[bi*PP + p];

#pragma unroll
    for (int j = 0; j < 4; j++) {
        int e = lane + (j << 5);
        float v = emb_b[e] + proj_b[e] + g_pos[l*EE + e];
#pragma unroll
        for (int p = 0; p < PP; p++)
            v += xr[p] * emb_w[e*PP + p] + sel[p] * proj_w[e*PP + p];
        g_seq[(size_t)rid*EE + e] = v;
    }
}

// ========== tf32 mma GEMM v5: C[M,N] = A[M,Kd] @ W[N,Kd]^T + bias ============
// 256 threads = 8 warps arranged 4(m) x 2(n); warp tile 32 rows x NT/2 cols
// (2 m-frags, NF2 = NT/16 col-frags). B pre-packed in fragment order, each
// n-warp reads only its half. ACT=1: ELU. FLN=1: fused residual+layernorm via
// smem cross-warp reduction (NT==N==128; C updated in place).
template <int NT, int ACT, int FLN>
__global__ __launch_bounds__(256, 2)
void mma_gemm5(const float* __restrict__ A, const float* __restrict__ W,
               const float* __restrict__ bias, float* __restrict__ C,
               const float* __restrict__ gam, const float* __restrict__ bet,
               int N, int Kd)
{
    constexpr int NF  = NT/8;                 // total 8-col fragments (16 or 8)
    constexpr int NF2 = NF/2;                 // fragments per n-warp (8 or 4)
    constexpr int NFp = (NF == 16) ? 20 : 12; // 4*odd: conflict-free vec4 LDS
    constexpr int SA  = 132;
    __shared__ __align__(16) uint32_t As [32*SA];
    __shared__ __align__(16) uint32_t Bp0[4*32*NFp];
    __shared__ __align__(16) uint32_t Bp1[4*32*NFp];
    __shared__ float sred[128*2*2];           // [row][wn][sum|sq] (FLN only)
    int tid = threadIdx.x;
    int w = tid >> 5, lane = tid & 31;
    int wn = w & 1, wm = w >> 1;
    int lq = lane >> 2, lr = lane & 3;
    int m0 = blockIdx.y << 7, n0 = blockIdx.x * NT;
    int mw = wm << 5;                          // warp row base (32 rows)

    float acc[2][NF2][4];
#pragma unroll
    for (int f = 0; f < 2; f++)
#pragma unroll
        for (int j = 0; j < NF2; j++)
#pragma unroll
            for (int t = 0; t < 4; t++) acc[f][j][t] = 0.f;

    for (int k0 = 0; k0 < Kd; k0 += 32) {
#pragma unroll
        for (int i = 0; i < 4; i++) {               // A: 128 rows x 32 k
            int idx = tid + (i << 8);
            int m = idx >> 3, g = idx & 7;
            float4 v = *(const float4*)(A + (size_t)(m0 + m) * Kd + k0 + g*4);
            As[(g*4+0)*SA + m] = tf32c(v.x);
            As[(g*4+1)*SA + m] = tf32c(v.y);
            As[(g*4+2)*SA + m] = tf32c(v.z);
            As[(g*4+3)*SA + m] = tf32c(v.w);
        }
#pragma unroll
        for (int i = 0; i < NT/32; i++) {           // B: NT rows x 32 k, packed
            int idx = tid + (i << 8);
            int n = idx >> 3, g = idx & 7;
            float4 v = *(const float4*)(W + (size_t)(n0 + n) * Kd + k0 + g*4);
            uint32_t* dst = ((g & 1) ? Bp1 : Bp0)
                          + (((g >> 1)*32) + ((n & 7) << 2))*NFp + (n >> 3);
            dst[0*NFp] = tf32c(v.x);
            dst[1*NFp] = tf32c(v.y);
            dst[2*NFp] = tf32c(v.z);
            dst[3*NFp] = tf32c(v.w);
        }
        __syncthreads();
#pragma unroll
        for (int k8 = 0; k8 < 4; k8++) {
            int kk = k8*8;
            uint32_t a[2][4];
#pragma unroll
            for (int f = 0; f < 2; f++) {
                a[f][0] = As[(kk + lr)*SA + mw + f*16 + lq];
                a[f][1] = As[(kk + lr)*SA + mw + f*16 + 8 + lq];
                a[f][2] = As[(kk + 4 + lr)*SA + mw + f*16 + lq];
                a[f][3] = As[(kk + 4 + lr)*SA + mw + f*16 + 8 + lq];
            }
            const uint32_t* bp0 = Bp0 + (k8*32 + lane)*NFp + wn*NF2;
            const uint32_t* bp1 = Bp1 + (k8*32 + lane)*NFp + wn*NF2;
#pragma unroll
            for (int jv = 0; jv < NF2/4; jv++) {
                uint4 b0v = *(const uint4*)(bp0 + jv*4);
                uint4 b1v = *(const uint4*)(bp1 + jv*4);
#pragma unroll
                for (int f = 0; f < 2; f++) {
                    mma8(acc[f][jv*4+0], a[f][0],a[f][1],a[f][2],a[f][3], b0v.x, b1v.x);
                    mma8(acc[f][jv*4+1], a[f][0],a[f][1],a[f][2],a[f][3], b0v.y, b1v.y);
                    mma8(acc[f][jv*4+2], a[f][0],a[f][1],a[f][2],a[f][3], b0v.z, b1v.z);
                    mma8(acc[f][jv*4+3], a[f][0],a[f][1],a[f][2],a[f][3], b0v.w, b1v.w);
                }
            }
        }
        __syncthreads();
    }

    if (!FLN) {
#pragma unroll
        for (int f = 0; f < 2; f++) {
            int r0 = m0 + mw + f*16 + lq;
#pragma unroll
            for (int j = 0; j < NF2; j++) {
                int n = n0 + (wn*NF2 + j)*8 + 2*lr;
                float2 bv = *(const float2*)(bias + n);
                float x0 = acc[f][j][0] + bv.x, x1 = acc[f][j][1] + bv.y;
                float x2 = acc[f][j][2] + bv.x, x3 = acc[f][j][3] + bv.y;
                if (ACT) {
                    x0 = (x0 > 0.f) ? x0 : expm1f(x0);
                    x1 = (x1 > 0.f) ? x1 : expm1f(x1);
                    x2 = (x2 > 0.f) ? x2 : expm1f(x2);
                    x3 = (x3 > 0.f) ? x3 : expm1f(x3);
                }
                float2 o0; o0.x = x0; o0.y = x1;
                float2 o1; o1.x = x2; o1.y = x3;
                *(float2*)(C + (size_t)r0 * N + n)     = o0;
                *(float2*)(C + (size_t)(r0+8) * N + n) = o1;
            }
        }
    } else {
        // bias + residual add
#pragma unroll
        for (int f = 0; f < 2; f++) {
            int r0 = m0 + mw + f*16 + lq;
#pragma unroll
            for (int j = 0; j < NF2; j++) {
                int n = (wn*NF2 + j)*8 + 2*lr;
                float2 bv = *(const float2*)(bias + n);
                float2 e0 = *(const float2*)(C + (size_t)r0*128 + n);
                float2 e1 = *(const float2*)(C + (size_t)(r0+8)*128 + n);
                acc[f][j][0] += bv.x + e0.x;  acc[f][j][1] += bv.y + e0.y;
                acc[f][j][2] += bv.x + e1.x;  acc[f][j][3] += bv.y + e1.y;
            }
        }
        // per-thread partials over this warp's 64 cols; idx = f*2 + half
        float ps[4] = {0.f,0.f,0.f,0.f}, pq[4] = {0.f,0.f,0.f,0.f};
#pragma unroll
        for (int f = 0; f < 2; f++)
#pragma unroll
            for (int j = 0; j < NF2; j++) {
                ps[f*2+0] += acc[f][j][0] + acc[f][j][1];
                pq[f*2+0] += acc[f][j][0]*acc[f][j][0] + acc[f][j][1]*acc[f][j][1];
                ps[f*2+1] += acc[f][j][2] + acc[f][j][3];
                pq[f*2+1] += acc[f][j][2]*acc[f][j][2] + acc[f][j][3]*acc[f][j][3];
            }
#pragma unroll
        for (int i = 0; i < 4; i++) {
            ps[i] += __shfl_xor_sync(0xffffffffu, ps[i], 1);
            ps[i] += __shfl_xor_sync(0xffffffffu, ps[i], 2);
            pq[i] += __shfl_xor_sync(0xffffffffu, pq[i], 1);
            pq[i] += __shfl_xor_sync(0xffffffffu, pq[i], 2);
        }
        if (lr == 0) {
#pragma unroll
            for (int i = 0; i < 4; i++) {
                int ridx = mw + (i >> 1)*16 + (i & 1)*8 + lq;
                sred[(ridx*2 + wn)*2 + 0] = ps[i];
                sred[(ridx*2 + wn)*2 + 1] = pq[i];
            }
        }
        __syncthreads();
        float mean[4], rstd[4];
#pragma unroll
        for (int i = 0; i < 4; i++) {
            int ridx = mw + (i >> 1)*16 + (i & 1)*8 + lq;
            float s  = sred[(ridx*2 + 0)*2 + 0] + sred[(ridx*2 + 1)*2 + 0];
            float sq = sred[(ridx*2 + 0)*2 + 1] + sred[(ridx*2 + 1)*2 + 1];
            mean[i] = s * (1.0f/128.0f);
            float var = sq * (1.0f/128.0f) - mean[i]*mean[i];
            rstd[i] = rsqrtf(var + 1e-5f);
        }
#pragma unroll
        for (int f = 0; f < 2; f++) {
            int r0 = m0 + mw + f*16 + lq;
            float m0v = mean[f*2+0], r0v = rstd[f*2+0];
            float m1v = mean[f*2+1], r1v = rstd[f*2+1];
#pragma unroll
            for (int j = 0; j < NF2; j++) {
                int n = (wn*NF2 + j)*8 + 2*lr;
                float2 gv = *(const float2*)(gam + n);
                float2 bt = *(const float2*)(bet + n);
                float2 o0, o1;
                o0.x = (acc[f][j][0] - m0v)*r0v*gv.x + bt.x;
                o0.y = (acc[f][j][1] - m0v)*r0v*gv.y + bt.y;
                o1.x = (acc[f][j][2] - m1v)*r1v*gv.x + bt.x;
                o1.y = (acc[f][j][3] - m1v)*r1v*gv.y + bt.y;
                *(float2*)(C + (size_t)r0*128 + n)     = o0;
                *(float2*)(C + (size_t)(r0+8)*128 + n) = o1;
            }
        }
    }
}

// ========== attention on mma.sync: block=(qtile,h,b), 256 thr, 8 warps ========
#define ACH 64
#define NCHUNK (LL/ACH)   // 12
__global__ __launch_bounds__(256)
void attn_mma_kernel(const float* __restrict__ qkv, float* __restrict__ ctx)
{
    __shared__ uint32_t Ks[ACH*20];
    __shared__ uint32_t Vs[ACH*24];
    int qt = blockIdx.x, h = blockIdx.y, b = blockIdx.z;
    int tid = threadIdx.x;
    int w = tid >> 5, lane = tid & 31;
    int lq = lane >> 2, lr = lane & 3;
    const float SC = 0.25f * 1.4426950408889634f;
    const float* base = qkv + (size_t)b * LL * (3*EE) + h*HD;

    uint32_t qa[2][4];
    {
        const float* q0 = base + (size_t)(qt*128 + w*16 + lq) * (3*EE);
        const float* q1 = q0 + (size_t)8 * (3*EE);
#pragma unroll
        for (int ks = 0; ks < 2; ks++) {
            qa[ks][0] = tf32c(q0[ks*8 + lr]     * SC);
            qa[ks][1] = tf32c(q1[ks*8 + lr]     * SC);
            qa[ks][2] = tf32c(q0[ks*8 + 4 + lr] * SC);
            qa[ks][3] = tf32c(q1[ks*8 + 4 + lr] * SC);
        }
    }

    float acc[2][4];
#pragma unroll
    for (int nf = 0; nf < 2; nf++)
#pragma unroll
        for (int t = 0; t < 4; t++) acc[nf][t] = 0.f;
    float s0 = 0.f, s1 = 0.f;

    for (int c = 0; c < NCHUNK; c++) {
        __syncthreads();
        {
            int m = tid >> 2, part = (tid & 3) << 2;
            const float* kp = base + (size_t)(c*ACH + m) * (3*EE) + EE + part;
            float4 kv = *(const float4*)kp;
            float4 vv = *(const float4*)(kp + EE);
            Ks[m*20 + part + 0] = tf32c(kv.x);
            Ks[m*20 + part + 1] = tf32c(kv.y);
            Ks[m*20 + part + 2] = tf32c(kv.z);
            Ks[m*20 + part + 3] = tf32c(kv.w);
            Vs[m*24 + part + 0] = tf32c(vv.x);
            Vs[m*24 + part + 1] = tf32c(vv.y);
            Vs[m*24 + part + 2] = tf32c(vv.z);
            Vs[m*24 + part + 3] = tf32c(vv.w);
        }
        __syncthreads();

#pragma unroll
        for (int j = 0; j < 8; j++) {
            float sf[4] = {0.f, 0.f, 0.f, 0.f};
#pragma unroll
            for (int ks = 0; ks < 2; ks++) {
                uint32_t b0 = Ks[(j*8 + lq)*20 + ks*8 + lr];
                uint32_t b1 = Ks[(j*8 + lq)*20 + ks*8 + 4 + lr];
                mma8(sf, qa[ks][0], qa[ks][1], qa[ks][2], qa[ks][3], b0, b1);
            }
            float e0 = ex2f(sf[0]), e1 = ex2f(sf[1]);
            float e2 = ex2f(sf[2]), e3 = ex2f(sf[3]);
            s0 += e0 + e1;  s1 += e2 + e3;
            uint32_t f0 = tf32c(e0), f1 = tf32c(e1);
            uint32_t f2 = tf32c(e2), f3 = tf32c(e3);
            int src0 = (lane & 28) | (lr >> 1);
            int src2 = src0 + 2;
            uint32_t t00 = __shfl_sync(0xffffffffu, f0, src0);
            uint32_t t01 = __shfl_sync(0xffffffffu, f1, src0);
            uint32_t t02 = __shfl_sync(0xffffffffu, f2, src0);
            uint32_t t03 = __shfl_sync(0xffffffffu, f3, src0);
            uint32_t t20 = __shfl_sync(0xffffffffu, f0, src2);
            uint32_t t21 = __shfl_sync(0xffffffffu, f1, src2);
            uint32_t t22 = __shfl_sync(0xffffffffu, f2, src2);
            uint32_t t23 = __shfl_sync(0xffffffffu, f3, src2);
            bool odd = (lr & 1);
            uint32_t a0 = odd ? t01 : t00;
            uint32_t a1 = odd ? t03 : t02;
            uint32_t a2 = odd ? t21 : t20;
            uint32_t a3 = odd ? t23 : t22;
#pragma unroll
            for (int nf = 0; nf < 2; nf++) {
                uint32_t b0 = Vs[(j*8 + lr)*24 + nf*8 + lq];
                uint32_t b1 = Vs[(j*8 + 4 + lr)*24 + nf*8 + lq];
                mma8(acc[nf], a0, a1, a2, a3, b0, b1);
            }
        }
    }

    s0 += __shfl_xor_sync(0xffffffffu, s0, 1);
    s0 += __shfl_xor_sync(0xffffffffu, s0, 2);
    s1 += __shfl_xor_sync(0xffffffffu, s1, 1);
    s1 += __shfl_xor_sync(0xffffffffu, s1, 2);
    float inv0 = 1.0f / s0, inv1 = 1.0f / s1;

    float* o0 = ctx + (size_t)(b*LL + qt*128 + w*16 + lq) * EE + h*HD;
    float* o1 = o0 + (size_t)8 * EE;
#pragma unroll
    for (int nf = 0; nf < 2; nf++) {
        float2 r0; r0.x = acc[nf][0] * inv0;  r0.y = acc[nf][1] * inv0;
        float2 r1; r1.x = acc[nf][2] * inv1;  r1.y = acc[nf][3] * inv1;
        *(float2*)(o0 + nf*8 + 2*lr) = r0;
        *(float2*)(o1 + nf*8 + 2*lr) = r1;
    }
}

// ========== final projection on mma: block per l, 128 thr, 4 warps ===========
__global__ __launch_bounds__(128)
void final_mma(const float* __restrict__ seq, const float* __restrict__ ow,
               float* __restrict__ part)
{
    constexpr int NFp = 20;
    constexpr int SAE = 36;
    __shared__ __align__(16) uint32_t Ae [128*SAE];
    __shared__ __align__(16) uint32_t Bp0[4*32*NFp];
    __shared__ __align__(16) uint32_t Bp1[4*32*NFp];
    int l = blockIdx.x, tid = threadIdx.x;
    int w = tid >> 5, lane = tid & 31;
    int lq = lane >> 2, lr = lane & 3;

#pragma unroll
    for (int i = 0; i < 8; i++) {
        int idx = tid + (i << 7);
        int b = idx >> 5, g = idx & 31;
        float4 v = *(const float4*)(seq + (size_t)b*(LL*EE) + l*EE + g*4);
        Ae[(g*4+0)*SAE + b] = tf32c(v.x);
        Ae[(g*4+1)*SAE + b] = tf32c(v.y);
        Ae[(g*4+2)*SAE + b] = tf32c(v.z);
        Ae[(g*4+3)*SAE + b] = tf32c(v.w);
    }

    float acc[2][4][4];
#pragma unroll
    for (int f = 0; f < 2; f++)
#pragma unroll
        for (int j = 0; j < 4; j++)
#pragma unroll
            for (int t = 0; t < 4; t++) acc[f][j][t] = 0.f;

    for (int k0 = 0; k0 < 128; k0 += 32) {
#pragma unroll
        for (int i = 0; i < 8; i++) {
            int idx = tid + (i << 7);
            int n = idx >> 3, g = idx & 7;
            float4 v = *(const float4*)(ow + (size_t)n*(LL*EE) + l*EE + k0 + g*4);
            uint32_t* dst = ((g & 1) ? Bp1 : Bp0)
                          + (((g >> 1)*32) + ((n & 7) << 2))*NFp + (n >> 3);
            dst[0*NFp] = tf32c(v.x);
            dst[1*NFp] = tf32c(v.y);
            dst[2*NFp] = tf32c(v.z);
            dst[3*NFp] = tf32c(v.w);
        }
        __syncthreads();
#pragma unroll
        for (int k8 = 0; k8 < 4; k8++) {
            int kk = k0 + k8*8;
            uint32_t a0[4], a1[4];
            a0[0] = Ae[(kk + lr)*SAE + lq];
            a0[1] = Ae[(kk + lr)*SAE + 8 + lq];
            a0[2] = Ae[(kk + 4 + lr)*SAE + lq];
            a0[3] = Ae[(kk + 4 + lr)*SAE + 8 + lq];
            a1[0] = Ae[(kk + lr)*SAE + 16 + lq];
            a1[1] = Ae[(kk + lr)*SAE + 24 + lq];
            a1[2] = Ae[(kk + 4 + lr)*SAE + 16 + lq];
            a1[3] = Ae[(kk + 4 + lr)*SAE + 24 + lq];
            const uint32_t* bp0 = Bp0 + (k8*32 + lane)*NFp + (w << 2);
            const uint32_t* bp1 = Bp1 + (k8*32 + lane)*NFp + (w << 2);
            uint4 b0v = *(const uint4*)bp0;
            uint4 b1v = *(const uint4*)bp1;
            mma8(acc[0][0], a0[0],a0[1],a0[2],a0[3], b0v.x, b1v.x);
            mma8(acc[1][0], a1[0],a1[1],a1[2],a1[3], b0v.x, b1v.x);
            mma8(acc[0][1], a0[0],a0[1],a0[2],a0[3], b0v.y, b1v.y);
            mma8(acc[1][1], a1[0],a1[1],a1[2],a1[3], b0v.y, b1v.y);
            mma8(acc[0][2], a0[0],a0[1],a0[2],a0[3], b0v.z, b1v.z);
            mma8(acc[1][2], a1[0],a1[1],a1[2],a1[3], b0v.z, b1v.z);
            mma8(acc[0][3], a0[0],a0[1],a0[2],a0[3], b0v.w, b1v.w);
            mma8(acc[1][3], a1[0],a1[1],a1[2],a1[3], b0v.w, b1v.w);
        }
        __syncthreads();
    }

    float* dst = part + (size_t)l * (BB*OUTN);
#pragma unroll
    for (int f = 0; f < 2; f++) {
        int br = f*16 + lq;
#pragma unroll
        for (int j = 0; j < 4; j++) {
            int o = (w << 5) + j*8 + 2*lr;
            float2 v0; v0.x = acc[f][j][0]; v0.y = acc[f][j][1];
            float2 v1; v1.x = acc[f][j][2]; v1.y = acc[f][j][3];
            *(float2*)(dst + br*OUTN + o)     = v0;
            *(float2*)(dst + (br+8)*OUTN + o) = v1;
        }
    }
}

// ---------------- final reduce: one warp per output ----------------
__global__ __launch_bounds__(256)
void final_reduce2(const float* __restrict__ part,
                   const float* __restrict__ out_b, float* __restrict__ out)
{
    int gw = (blockIdx.x * 256 + threadIdx.x) >> 5;
    int lane = threadIdx.x & 31;
    float s = 0.f;
#pragma unroll
    for (int t = 0; t < 24; t++)
        s += part[(size_t)(lane + t*32) * (BB*OUTN) + gw];
#pragma unroll
    for (int o = 16; o > 0; o >>= 1) s += __shfl_xor_sync(0xffffffffu, s, o);
    if (lane == 0) out[gw] = s + out_b[gw & 127];
}

// ---------------- host launcher ----------------
extern "C" void kernel_launch(void* const* d_in, const int* in_sizes, int n_in,
                              void* d_out, int out_size)
{
    const float* x          = (const float*)d_in[0];
    const float* prototypes = (const float*)d_in[1];
    const float* emb_w      = (const float*)d_in[2];
    const float* emb_b      = (const float*)d_in[3];
    const float* proj_w     = (const float*)d_in[4];
    const float* proj_b     = (const float*)d_in[5];
    const float* in_proj_w  = (const float*)d_in[6];
    const float* in_proj_b  = (const float*)d_in[7];
    const float* out_proj_w = (const float*)d_in[8];
    const float* out_proj_b = (const float*)d_in[9];
    const float* ln1_s      = (const float*)d_in[10];
    const float* ln1_b      = (const float*)d_in[11];
    const float* ffn_w1     = (const float*)d_in[12];
    const float* ffn_b1     = (const float*)d_in[13];
    const float* ffn_w2     = (const float*)d_in[14];
    const float* ffn_b2     = (const float*)d_in[15];
    const float* ln2_s      = (const float*)d_in[16];
    const float* ln2_b      = (const float*)d_in[17];
    const float* out_w      = (const float*)d_in[18];
    const float* out_b      = (const float*)d_in[19];
    float* out = (float*)d_out;

    float *seq, *qkv, *ctx, *hid, *part;
    cudaGetSymbolAddress((void**)&seq,   g_seq);
    cudaGetSymbolAddress((void**)&qkv,   g_qkv);
    cudaGetSymbolAddress((void**)&ctx,   g_ctx);
    cudaGetSymbolAddress((void**)&hid,   g_hid);
    cudaGetSymbolAddress((void**)&part,  g_part);

    proto_norm_kernel<<<12, 256>>>(prototypes);
    pos_kernel<<<(LL*EE)/256, 256>>>();
    embed_kernel<<<BLR/8, 256>>>(x, emb_w, emb_b, proj_w, proj_b);

    for (int l = 0; l < 2; l++) {
        // qkv = seq @ in_proj_w[l]^T + b   (M=24576, N=384, K=128)
        mma_gemm5<128,0,0><<<dim3(3, BLR/128), 256>>>(
            seq, in_proj_w + (size_t)l*3*EE*EE, in_proj_b + l*3*EE, qkv,
            nullptr, nullptr, 3*EE, EE);
        attn_mma_kernel<<<dim3(LL/128, HH, BB), 256>>>(qkv, ctx);
        // seq = LN1(seq + ctx @ out_proj_w[l]^T + b)   (fused)
        mma_gemm5<128,0,1><<<dim3(1, BLR/128), 256>>>(
            ctx, out_proj_w + (size_t)l*EE*EE, out_proj_b + l*EE, seq,
            ln1_s + l*EE, ln1_b + l*EE, EE, EE);
        // hid = elu(seq @ w1^T + b1)   (N=64, K=128)
        mma_gemm5<64,1,0><<<dim3(1, BLR/128), 256>>>(
            seq, ffn_w1 + (size_t)l*II*EE, ffn_b1 + l*II, hid,
            nullptr, nullptr, II, EE);
        // seq = LN2(seq + hid @ w2^T + b2)   (fused; K=64)
        mma_gemm5<128,0,1><<<dim3(1, BLR/128), 256>>>(
            hid, ffn_w2 + (size_t)l*EE*II, ffn_b2 + l*EE, seq,
            ln2_s + l*EE, ln2_b + l*EE, EE, II);
    }

    final_mma<<<LL, 128>>>(seq, out_w, part);
    final_reduce2<<<(BB*OUTN*32)/256, 256>>>(part, out_b, out);
}